// round 15
// baseline (speedup 1.0000x reference)
#include <cuda_runtime.h>
#include <cuda_fp16.h>

// ---------------- problem constants ----------------
#define S_LEN   4096
#define HID     2048
#define NCTA    148
#define NTHR    256
#define M_TOT   64            // mmas per warp per step
#define R_REG   36            // mmas whose A fragments live in registers
#define M_SMEM  (M_TOT - R_REG)
#define SMEM_W_BYTES (8 * M_SMEM * 32 * 16)          // 114688
#define SMEM_HX_BYTES 4096
#define SMEM_BYTES (SMEM_W_BYTES + SMEM_HX_BYTES + 2 * 64 * 4)
#define SH_TOT  (S_LEN * HID)
#define NFRAG   ((size_t)NCTA * 8 * M_TOT * 32)

// ---------------- device scratch ----------------
__device__ uint4    g_wA[NFRAG];     // A-fragment-ordered fp16 weights
__device__ __align__(16) unsigned short g_img[(size_t)S_LEN * HID]; // f16 hx rows, B-frag permuted
__device__ float    g_c[S_LEN];
__device__ float    g_w0[HID * 4];
__device__ float    g_bias[HID * 4];
__device__ unsigned g_bar;           // monotonic barrier: 2048 lane-arrivals per step

// ---------------- helpers ----------------
__device__ __forceinline__ unsigned bar_ld(const unsigned *p) {
    unsigned v; asm volatile("ld.acquire.gpu.global.u32 %0,[%1];" : "=r"(v) : "l"(p)); return v;
}
__device__ __forceinline__ void bar_red(unsigned *p) {
    asm volatile("red.release.gpu.global.add.u32 [%0],1;" :: "l"(p));
}
__device__ __forceinline__ uint4 ld_cg4(const void *p) {
    uint4 v;
    asm volatile("ld.global.cg.v4.u32 {%0,%1,%2,%3},[%4];"
                 : "=r"(v.x), "=r"(v.y), "=r"(v.z), "=r"(v.w) : "l"(p));
    return v;
}
__device__ __forceinline__ float sigm(float x)      { return 1.f / (1.f + __expf(-x)); }
__device__ __forceinline__ float tanh_fast(float x) { return 2.f / (1.f + __expf(-2.f * x)) - 1.f; }
__device__ __forceinline__ unsigned h2pack(float x, float y) {
    __half2 h = __floats2half2_rn(x, y); return *(unsigned *)&h;
}

// ---------------- single merged prep kernel ----------------
__global__ void prep_all(const float *__restrict__ wg, const float *__restrict__ in,
                         const float *__restrict__ cw, const float *__restrict__ cb,
                         const float *__restrict__ bg) {
    size_t idx = (size_t)blockIdx.x * 256 + threadIdx.x;

    if (idx < NFRAG) {
        int lane = (int)(idx & 31);
        int m = (int)((idx >> 5) & (M_TOT - 1));
        int w = (int)((idx >> 11) & 7);
        int b = (int)(idx >> 14);
        int g = w & 3, h = w >> 2;
        int ustart = b * 13 + min(b, 124);
        int U4 = ((b < 124) ? 14 : 13) * 4;
        int d0 = g * 16 + (lane >> 2);
        int d1 = d0 + 8;
        int kb = h * 1024 + m * 16 + (lane & 3) * 2;
        auto W = [&](int d, int k) -> float {
            if (d >= U4) return 0.f;
            return wg[(size_t)(1 + k) * (4 * HID) + (d & 3) * HID + ustart + (d >> 2)];
        };
        uint4 v;
        v.x = h2pack(W(d0, kb),     W(d0, kb + 1));
        v.y = h2pack(W(d1, kb),     W(d1, kb + 1));
        v.z = h2pack(W(d0, kb + 8), W(d0, kb + 9));
        v.w = h2pack(W(d1, kb + 8), W(d1, kb + 9));
        g_wA[idx] = v;
    }
    if (idx < S_LEN) {
        float a = in[idx * 4 + 0] * cw[0] + in[idx * 4 + 1] * cw[1]
                + in[idx * 4 + 2] * cw[2] + in[idx * 4 + 3] * cw[3] + cb[0];
        g_c[idx] = 1.f / (1.f + __expf(-a));
    }
    if (idx < 4 * HID) {
        int g = (int)idx & 3, j = (int)idx >> 2;
        g_w0[idx]   = wg[g * HID + j];
        g_bias[idx] = bg[g * HID + j];
    }
    if (idx == 0) g_bar = 0;
}

// ---------------- main persistent LSTM kernel ----------------
__global__ __launch_bounds__(NTHR, 1) void lstm_main(float *__restrict__ out) {
    extern __shared__ unsigned char smem[];
    uint4    *wsall = (uint4 *)smem;                                   // [8][M_SMEM][32]
    unsigned *hxw   = (unsigned *)(smem + SMEM_W_BYTES);               // 1024 words
    uint4    *hx4   = (uint4 *)hxw;
    float    *red   = (float *)(smem + SMEM_W_BYTES + SMEM_HX_BYTES);  // [2][64]

    const int b = blockIdx.x;
    const int ustart = b * 13 + min(b, 124);
    const int U = (b < 124) ? 14 : 13;
    const int tid  = threadIdx.x;
    const int w    = tid >> 5;
    const int lane = tid & 31;
    const int g    = w & 3;
    const int h    = w >> 2;
    const int kc   = lane & 3;

    // Load this warp's A fragments: first R_REG to registers, rest to SMEM.
    const uint4 *gsrc = g_wA + ((size_t)(b * 8 + w) * M_TOT) * 32 + lane;
    uint4 areg[R_REG];
    #pragma unroll
    for (int m = 0; m < R_REG; m++) areg[m] = gsrc[(size_t)m * 32];
    uint4 *wsw = wsall + (w * M_SMEM) * 32 + lane;
    #pragma unroll
    for (int m = 0; m < M_SMEM; m++) wsw[m * 32] = gsrc[(size_t)(R_REG + m) * 32];

    float w0r[4], br[4], cx = 0.f, hv = 0.f;
    if (tid < U) {
        #pragma unroll
        for (int gg = 0; gg < 4; gg++) {
            w0r[gg] = g_w0[(ustart + tid) * 4 + gg];
            br[gg]  = g_bias[(ustart + tid) * 4 + gg];
        }
    }
    // precompute this thread's hx publish slot (B-frag permuted u16 address)
    int pub_off = 0;
    {
        int j = ustart + tid;
        int p = j >> 1;
        int wi = ((p >> 4) << 4) + (((p >> 3) & 1) << 1) + ((p >> 2) & 1) + ((p & 3) << 2);
        pub_off = wi * 2 + (j & 1);
    }
    __syncthreads();

    const uint4 *hxp = hx4 + (h * 32) * 4 + kc;

    for (int t = 0; t < S_LEN; t++) {
        // ---- hoisted conv-scalar load: issued ~1500 cyc before epilogue use ----
        float ct = 0.f;
        if (w == 0) ct = __ldg(&g_c[t]);

        // ---- stage hx(t-1): pre-permuted f16 image, identity copy GMEM->SMEM ----
        {
            uint4 v;
            if (t == 0) v = make_uint4(0u, 0u, 0u, 0u);
            else        v = ld_cg4((const uint4 *)(g_img + (size_t)(t - 1) * HID) + tid);
            ((uint4 *)hxw)[tid] = v;
        }
        __syncthreads();

        // ---- matvec: 64 HMMA.16816 per warp, 4 independent accumulator chains ----
        float c0[4] = {0.f, 0.f, 0.f, 0.f};
        float c1[4] = {0.f, 0.f, 0.f, 0.f};
        float c2[4] = {0.f, 0.f, 0.f, 0.f};
        float c3[4] = {0.f, 0.f, 0.f, 0.f};
        uint4 bv;
        #pragma unroll
        for (int m = 0; m < M_TOT; m++) {
            if ((m & 1) == 0) bv = hxp[(m >> 1) * 4];
            uint4 av = (m < R_REG) ? areg[m] : wsw[(m - R_REG) * 32];
            unsigned blo = (m & 1) ? bv.z : bv.x;
            unsigned bhi = (m & 1) ? bv.w : bv.y;
            float *C = ((m & 3) == 0) ? c0 : ((m & 3) == 1) ? c1 : ((m & 3) == 2) ? c2 : c3;
            asm("mma.sync.aligned.m16n8k16.row.col.f32.f16.f16.f32 "
                "{%0,%1,%2,%3},{%4,%5,%6,%7},{%8,%9},{%0,%1,%2,%3};"
                : "+f"(C[0]), "+f"(C[1]), "+f"(C[2]), "+f"(C[3])
                : "r"(av.x), "r"(av.y), "r"(av.z), "r"(av.w),
                  "r"(blo), "r"(bhi));
        }

        // ---- export partial dots ----
        if ((lane & 3) == 0) {
            int r = lane >> 2;
            red[h * 64 + g * 16 + r]     = c0[0] + c1[0] + c2[0] + c3[0];
            red[h * 64 + g * 16 + 8 + r] = c0[2] + c1[2] + c2[2] + c3[2];
        }
        __syncthreads();

        // ---- dedicated poller (warp 1, lane 0): spins concurrently with epilogue ----
        if (tid == 32) {
            const unsigned tgt = (unsigned)HID * (unsigned)(t + 1);   // 2048 lane-arrivals/step
            while (bar_ld(&g_bar) < tgt) { }
        }

        // ---- epilogue (warp 0): gates, state, publish, per-lane release-arrive ----
        if (w == 0) {
            if (tid < U) {
                float4 ra = *(const float4 *)&red[tid * 4];
                float4 rb = *(const float4 *)&red[64 + tid * 4];
                float a0 = ra.x + rb.x + ct * w0r[0] + br[0];
                float a1 = ra.y + rb.y + ct * w0r[1] + br[1];
                float a2 = ra.z + rb.z + ct * w0r[2] + br[2];
                float a3 = ra.w + rb.w + ct * w0r[3] + br[3];
                float f  = sigm(a0);
                float ii = sigm(a1);
                float gg = tanh_fast(a2);
                float oo = sigm(a3);
                cx = f * cx + ii * gg;
                hv = oo * tanh_fast(cx);
                // publish pre-permuted f16, then per-lane release-arrive:
                // each lane's red.release covers exactly its own prior store;
                // 14 same-address lane-reds coalesce into one REDG instruction.
                unsigned short hb = __half_as_ushort(__float2half_rn(hv));
                asm volatile("st.global.cg.u16 [%0],%1;"
                             :: "l"(g_img + (size_t)t * HID + pub_off), "h"(hb));
                bar_red(&g_bar);
                // f32 output row: off the critical path, no cross-SM ordering needed
                out[(size_t)t * HID + ustart + tid] = hv;
            }
        }
        __syncthreads();
    }

    // final hx / cx rows (state lives in warp-0 lanes)
    if (w == 0 && tid < U) {
        int j = ustart + tid;
        out[SH_TOT + j]       = hv;
        out[SH_TOT + HID + j] = cx;
    }
}

// ---------------- launch ----------------
extern "C" void kernel_launch(void *const *d_in, const int *in_sizes, int n_in,
                              void *d_out, int out_size) {
    const float *inputs = nullptr, *cw = nullptr, *cb = nullptr, *wg = nullptr, *bg = nullptr;
    for (int i = 0; i < n_in; i++) {
        switch (in_sizes[i]) {
            case S_LEN * 4:        inputs = (const float *)d_in[i]; break;
            case 4:                cw     = (const float *)d_in[i]; break;
            case 1:                cb     = (const float *)d_in[i]; break;
            case 2049 * 4 * HID:   wg     = (const float *)d_in[i]; break;
            case 4 * HID:          bg     = (const float *)d_in[i]; break;
        }
    }
    float *out = (float *)d_out;

    static bool attr_set = false;
    if (!attr_set) {
        cudaFuncSetAttribute(lstm_main, cudaFuncAttributeMaxDynamicSharedMemorySize, SMEM_BYTES);
        attr_set = true;
    }

    prep_all<<<(int)((NFRAG + 255) / 256), 256>>>(wg, inputs, cw, cb, bg);
    lstm_main<<<NCTA, NTHR, SMEM_BYTES>>>(out);
}

// round 16
// speedup vs baseline: 1.4307x; 1.4307x over previous
#include <cuda_runtime.h>
#include <cuda_fp16.h>

// ---------------- problem constants ----------------
#define S_LEN   4096
#define HID     2048
#define NCTA    148
#define NTHR    256
#define M_TOT   64            // mmas per warp per step
#define R_REG   36            // mmas whose A fragments live in registers
#define M_SMEM  (M_TOT - R_REG)
#define SMEM_W_BYTES (8 * M_SMEM * 32 * 16)          // 114688
#define SMEM_HX_BYTES 4096
#define SMEM_BYTES (SMEM_W_BYTES + SMEM_HX_BYTES + 2 * 64 * 4)
#define SH_TOT  (S_LEN * HID)
#define NFRAG   ((size_t)NCTA * 8 * M_TOT * 32)

// ---------------- device scratch ----------------
__device__ uint4    g_wA[NFRAG];     // A-fragment-ordered fp16 weights
__device__ __align__(16) unsigned short g_img[(size_t)S_LEN * HID]; // f16 hx rows, B-frag permuted
__device__ float    g_c[S_LEN];
__device__ float    g_w0[HID * 4];
__device__ float    g_bias[HID * 4];
__device__ unsigned g_bar;           // monotonic grid barrier counter

// ---------------- helpers ----------------
__device__ __forceinline__ unsigned bar_ld(const unsigned *p) {
    unsigned v; asm volatile("ld.acquire.gpu.global.u32 %0,[%1];" : "=r"(v) : "l"(p)); return v;
}
__device__ __forceinline__ void bar_red(unsigned *p) {
    asm volatile("red.release.gpu.global.add.u32 [%0],1;" :: "l"(p));
}
__device__ __forceinline__ uint4 ld_cg4(const void *p) {
    uint4 v;
    asm volatile("ld.global.cg.v4.u32 {%0,%1,%2,%3},[%4];"
                 : "=r"(v.x), "=r"(v.y), "=r"(v.z), "=r"(v.w) : "l"(p));
    return v;
}
__device__ __forceinline__ float sigm(float x)      { return 1.f / (1.f + __expf(-x)); }
__device__ __forceinline__ float tanh_fast(float x) { return 2.f / (1.f + __expf(-2.f * x)) - 1.f; }
__device__ __forceinline__ unsigned h2pack(float x, float y) {
    __half2 h = __floats2half2_rn(x, y); return *(unsigned *)&h;
}

// ---------------- single merged prep kernel ----------------
__global__ void prep_all(const float *__restrict__ wg, const float *__restrict__ in,
                         const float *__restrict__ cw, const float *__restrict__ cb,
                         const float *__restrict__ bg) {
    size_t idx = (size_t)blockIdx.x * 256 + threadIdx.x;

    if (idx < NFRAG) {
        int lane = (int)(idx & 31);
        int m = (int)((idx >> 5) & (M_TOT - 1));
        int w = (int)((idx >> 11) & 7);
        int b = (int)(idx >> 14);
        int g = w & 3, h = w >> 2;
        int ustart = b * 13 + min(b, 124);
        int U4 = ((b < 124) ? 14 : 13) * 4;
        int d0 = g * 16 + (lane >> 2);
        int d1 = d0 + 8;
        int kb = h * 1024 + m * 16 + (lane & 3) * 2;
        auto W = [&](int d, int k) -> float {
            if (d >= U4) return 0.f;
            return wg[(size_t)(1 + k) * (4 * HID) + (d & 3) * HID + ustart + (d >> 2)];
        };
        uint4 v;
        v.x = h2pack(W(d0, kb),     W(d0, kb + 1));
        v.y = h2pack(W(d1, kb),     W(d1, kb + 1));
        v.z = h2pack(W(d0, kb + 8), W(d0, kb + 9));
        v.w = h2pack(W(d1, kb + 8), W(d1, kb + 9));
        g_wA[idx] = v;
    }
    if (idx < S_LEN) {
        float a = in[idx * 4 + 0] * cw[0] + in[idx * 4 + 1] * cw[1]
                + in[idx * 4 + 2] * cw[2] + in[idx * 4 + 3] * cw[3] + cb[0];
        g_c[idx] = 1.f / (1.f + __expf(-a));
    }
    if (idx < 4 * HID) {
        int g = (int)idx & 3, j = (int)idx >> 2;
        g_w0[idx]   = wg[g * HID + j];
        g_bias[idx] = bg[g * HID + j];
    }
    if (idx == 0) g_bar = 0;
}

// ---------------- main persistent LSTM kernel ----------------
__global__ __launch_bounds__(NTHR, 1) void lstm_main(float *__restrict__ out) {
    extern __shared__ unsigned char smem[];
    uint4    *wsall = (uint4 *)smem;                                   // [8][M_SMEM][32]
    unsigned *hxw   = (unsigned *)(smem + SMEM_W_BYTES);               // 1024 words
    uint4    *hx4   = (uint4 *)hxw;
    float    *red   = (float *)(smem + SMEM_W_BYTES + SMEM_HX_BYTES);  // [2][64]

    const int b = blockIdx.x;
    const int ustart = b * 13 + min(b, 124);
    const int U = (b < 124) ? 14 : 13;
    const int tid  = threadIdx.x;
    const int w    = tid >> 5;
    const int lane = tid & 31;
    const int g    = w & 3;
    const int h    = w >> 2;
    const int kc   = lane & 3;

    // Load this warp's A fragments: first R_REG to registers, rest to SMEM.
    const uint4 *gsrc = g_wA + ((size_t)(b * 8 + w) * M_TOT) * 32 + lane;
    uint4 areg[R_REG];
    #pragma unroll
    for (int m = 0; m < R_REG; m++) areg[m] = gsrc[(size_t)m * 32];
    uint4 *wsw = wsall + (w * M_SMEM) * 32 + lane;
    #pragma unroll
    for (int m = 0; m < M_SMEM; m++) wsw[m * 32] = gsrc[(size_t)(R_REG + m) * 32];

    float w0r[4], br[4], cx = 0.f, hv = 0.f;
    if (tid < U) {
        #pragma unroll
        for (int gg = 0; gg < 4; gg++) {
            w0r[gg] = g_w0[(ustart + tid) * 4 + gg];
            br[gg]  = g_bias[(ustart + tid) * 4 + gg];
        }
    }
    // precompute this thread's hx publish slot (B-frag permuted u16 address)
    int pub_off = 0;
    {
        int j = ustart + tid;
        int p = j >> 1;
        int wi = ((p >> 4) << 4) + (((p >> 3) & 1) << 1) + ((p >> 2) & 1) + ((p & 3) << 2);
        pub_off = wi * 2 + (j & 1);
    }
    __syncthreads();

    const uint4 *hxp = hx4 + (h * 32) * 4 + kc;

    for (int t = 0; t < S_LEN; t++) {
        // ---- hoisted conv-scalar load: issued ~1500 cyc before epilogue use ----
        float ct = 0.f;
        if (w == 0) ct = __ldg(&g_c[t]);

        // ---- stage hx(t-1): pre-permuted f16 image, identity copy GMEM->SMEM ----
        {
            uint4 v;
            if (t == 0) v = make_uint4(0u, 0u, 0u, 0u);
            else        v = ld_cg4((const uint4 *)(g_img + (size_t)(t - 1) * HID) + tid);
            ((uint4 *)hxw)[tid] = v;
        }
        __syncthreads();

        // ---- matvec: 64 HMMA.16816 per warp, 4 independent accumulator chains ----
        float c0[4] = {0.f, 0.f, 0.f, 0.f};
        float c1[4] = {0.f, 0.f, 0.f, 0.f};
        float c2[4] = {0.f, 0.f, 0.f, 0.f};
        float c3[4] = {0.f, 0.f, 0.f, 0.f};
        uint4 bv;
        #pragma unroll
        for (int m = 0; m < M_TOT; m++) {
            if ((m & 1) == 0) bv = hxp[(m >> 1) * 4];
            uint4 av = (m < R_REG) ? areg[m] : wsw[(m - R_REG) * 32];
            unsigned blo = (m & 1) ? bv.z : bv.x;
            unsigned bhi = (m & 1) ? bv.w : bv.y;
            float *C = ((m & 3) == 0) ? c0 : ((m & 3) == 1) ? c1 : ((m & 3) == 2) ? c2 : c3;
            asm("mma.sync.aligned.m16n8k16.row.col.f32.f16.f16.f32 "
                "{%0,%1,%2,%3},{%4,%5,%6,%7},{%8,%9},{%0,%1,%2,%3};"
                : "+f"(C[0]), "+f"(C[1]), "+f"(C[2]), "+f"(C[3])
                : "r"(av.x), "r"(av.y), "r"(av.z), "r"(av.w),
                  "r"(blo), "r"(bhi));
        }

        // ---- export partial dots ----
        if ((lane & 3) == 0) {
            int r = lane >> 2;
            red[h * 64 + g * 16 + r]     = c0[0] + c1[0] + c2[0] + c3[0];
            red[h * 64 + g * 16 + 8 + r] = c0[2] + c1[2] + c2[2] + c3[2];
        }
        __syncthreads();

        // ---- dedicated poller (warp 1, lane 0): spins concurrently with epilogue ----
        if (tid == 32) {
            const unsigned tgt = (unsigned)NCTA * (unsigned)(t + 1);
            while (bar_ld(&g_bar) < tgt) { }
        }

        // ---- epilogue (warp 0): gates, state, publish, release-arrive ----
        if (w == 0) {
            if (tid < U) {
                float4 ra = *(const float4 *)&red[tid * 4];
                float4 rb = *(const float4 *)&red[64 + tid * 4];
                float a0 = ra.x + rb.x + ct * w0r[0] + br[0];
                float a1 = ra.y + rb.y + ct * w0r[1] + br[1];
                float a2 = ra.z + rb.z + ct * w0r[2] + br[2];
                float a3 = ra.w + rb.w + ct * w0r[3] + br[3];
                float f  = sigm(a0);
                float ii = sigm(a1);
                float gg = tanh_fast(a2);
                float oo = sigm(a3);
                cx = f * cx + ii * gg;
                hv = oo * tanh_fast(cx);
                // publish pre-permuted f16 (ordered by syncwarp + red.release below)
                unsigned short hb = __half_as_ushort(__float2half_rn(hv));
                asm volatile("st.global.cg.u16 [%0],%1;"
                             :: "l"(g_img + (size_t)t * HID + pub_off), "h"(hb));
            }
            __syncwarp();
            if (tid == 0) bar_red(&g_bar);   // release-arrive covers the warp's stores
            // f32 output row: off the critical path, no cross-SM ordering needed
            if (tid < U) out[(size_t)t * HID + ustart + tid] = hv;
        }
        __syncthreads();
    }

    // final hx / cx rows (state lives in warp-0 lanes)
    if (w == 0 && tid < U) {
        int j = ustart + tid;
        out[SH_TOT + j]       = hv;
        out[SH_TOT + HID + j] = cx;
    }
}

// ---------------- launch ----------------
extern "C" void kernel_launch(void *const *d_in, const int *in_sizes, int n_in,
                              void *d_out, int out_size) {
    const float *inputs = nullptr, *cw = nullptr, *cb = nullptr, *wg = nullptr, *bg = nullptr;
    for (int i = 0; i < n_in; i++) {
        switch (in_sizes[i]) {
            case S_LEN * 4:        inputs = (const float *)d_in[i]; break;
            case 4:                cw     = (const float *)d_in[i]; break;
            case 1:                cb     = (const float *)d_in[i]; break;
            case 2049 * 4 * HID:   wg     = (const float *)d_in[i]; break;
            case 4 * HID:          bg     = (const float *)d_in[i]; break;
        }
    }
    float *out = (float *)d_out;

    static bool attr_set = false;
    if (!attr_set) {
        cudaFuncSetAttribute(lstm_main, cudaFuncAttributeMaxDynamicSharedMemorySize, SMEM_BYTES);
        attr_set = true;
    }

    prep_all<<<(int)((NFRAG + 255) / 256), 256>>>(wg, inputs, cw, cb, bg);
    lstm_main<<<NCTA, NTHR, SMEM_BYTES>>>(out);
}

// round 17
// speedup vs baseline: 1.4606x; 1.0209x over previous
#include <cuda_runtime.h>
#include <cuda_fp16.h>

// ---------------- problem constants ----------------
#define S_LEN   4096
#define HID     2048
#define NCTA    148
#define NTHR    256
#define M_TOT   64            // mmas per warp per step
#define R_REG   36            // mmas whose A fragments live in registers
#define M_SMEM  (M_TOT - R_REG)
#define SMEM_W_BYTES (8 * M_SMEM * 32 * 16)          // 114688
#define SMEM_HX_BYTES 4096
#define SMEM_BYTES (SMEM_W_BYTES + SMEM_HX_BYTES + 2 * 64 * 4)
#define SH_TOT  (S_LEN * HID)
#define NFRAG   ((size_t)NCTA * 8 * M_TOT * 32)

// ---------------- device scratch ----------------
__device__ uint4    g_wA[NFRAG];     // A-fragment-ordered fp16 weights
__device__ __align__(16) unsigned short g_img[(size_t)S_LEN * HID]; // f16 hx rows, B-frag permuted
__device__ float    g_c[S_LEN];
__device__ float    g_w0[HID * 4];
__device__ float    g_bias[HID * 4];
__device__ unsigned g_bar;           // monotonic grid barrier counter

// ---------------- helpers ----------------
__device__ __forceinline__ unsigned bar_ld(const unsigned *p) {
    unsigned v; asm volatile("ld.acquire.gpu.global.u32 %0,[%1];" : "=r"(v) : "l"(p)); return v;
}
__device__ __forceinline__ void bar_red(unsigned *p) {
    asm volatile("red.release.gpu.global.add.u32 [%0],1;" :: "l"(p));
}
__device__ __forceinline__ uint4 ld_cg4(const void *p) {
    uint4 v;
    asm volatile("ld.global.cg.v4.u32 {%0,%1,%2,%3},[%4];"
                 : "=r"(v.x), "=r"(v.y), "=r"(v.z), "=r"(v.w) : "l"(p));
    return v;
}
__device__ __forceinline__ float sigm(float x)      { return 1.f / (1.f + __expf(-x)); }
__device__ __forceinline__ float tanh_fast(float x) { return 2.f / (1.f + __expf(-2.f * x)) - 1.f; }
__device__ __forceinline__ unsigned h2pack(float x, float y) {
    __half2 h = __floats2half2_rn(x, y); return *(unsigned *)&h;
}

// ---------------- single merged prep kernel ----------------
__global__ void prep_all(const float *__restrict__ wg, const float *__restrict__ in,
                         const float *__restrict__ cw, const float *__restrict__ cb,
                         const float *__restrict__ bg) {
    size_t idx = (size_t)blockIdx.x * 256 + threadIdx.x;

    if (idx < NFRAG) {
        int lane = (int)(idx & 31);
        int m = (int)((idx >> 5) & (M_TOT - 1));
        int w = (int)((idx >> 11) & 7);
        int b = (int)(idx >> 14);
        int g = w & 3, h = w >> 2;
        int ustart = b * 13 + min(b, 124);
        int U4 = ((b < 124) ? 14 : 13) * 4;
        int d0 = g * 16 + (lane >> 2);
        int d1 = d0 + 8;
        int kb = h * 1024 + m * 16 + (lane & 3) * 2;
        auto W = [&](int d, int k) -> float {
            if (d >= U4) return 0.f;
            return wg[(size_t)(1 + k) * (4 * HID) + (d & 3) * HID + ustart + (d >> 2)];
        };
        uint4 v;
        v.x = h2pack(W(d0, kb),     W(d0, kb + 1));
        v.y = h2pack(W(d1, kb),     W(d1, kb + 1));
        v.z = h2pack(W(d0, kb + 8), W(d0, kb + 9));
        v.w = h2pack(W(d1, kb + 8), W(d1, kb + 9));
        g_wA[idx] = v;
    }
    if (idx < S_LEN) {
        float a = in[idx * 4 + 0] * cw[0] + in[idx * 4 + 1] * cw[1]
                + in[idx * 4 + 2] * cw[2] + in[idx * 4 + 3] * cw[3] + cb[0];
        g_c[idx] = 1.f / (1.f + __expf(-a));
    }
    if (idx < 4 * HID) {
        int g = (int)idx & 3, j = (int)idx >> 2;
        g_w0[idx]   = wg[g * HID + j];
        g_bias[idx] = bg[g * HID + j];
    }
    if (idx == 0) g_bar = 0;
}

// ---------------- main persistent LSTM kernel ----------------
__global__ __launch_bounds__(NTHR, 1) void lstm_main(float *__restrict__ out) {
    extern __shared__ unsigned char smem[];
    uint4    *wsall = (uint4 *)smem;                                   // [8][M_SMEM][32]
    unsigned *hxw   = (unsigned *)(smem + SMEM_W_BYTES);               // 1024 words
    uint4    *hx4   = (uint4 *)hxw;
    float    *red   = (float *)(smem + SMEM_W_BYTES + SMEM_HX_BYTES);  // [2][64]

    const int b = blockIdx.x;
    const int ustart = b * 13 + min(b, 124);
    const int U = (b < 124) ? 14 : 13;
    const int tid  = threadIdx.x;
    const int w    = tid >> 5;
    const int lane = tid & 31;
    const int g    = w & 3;
    const int h    = w >> 2;
    const int kc   = lane & 3;

    // Load this warp's A fragments: first R_REG to registers, rest to SMEM.
    const uint4 *gsrc = g_wA + ((size_t)(b * 8 + w) * M_TOT) * 32 + lane;
    uint4 areg[R_REG];
    #pragma unroll
    for (int m = 0; m < R_REG; m++) areg[m] = gsrc[(size_t)m * 32];
    uint4 *wsw = wsall + (w * M_SMEM) * 32 + lane;
    #pragma unroll
    for (int m = 0; m < M_SMEM; m++) wsw[m * 32] = gsrc[(size_t)(R_REG + m) * 32];

    float w0r[4], br[4], cx = 0.f, hv = 0.f;
    if (tid < U) {
        #pragma unroll
        for (int gg = 0; gg < 4; gg++) {
            w0r[gg] = g_w0[(ustart + tid) * 4 + gg];
            br[gg]  = g_bias[(ustart + tid) * 4 + gg];
        }
    }
    // precompute this thread's hx publish slot (B-frag permuted u16 address)
    int pub_off = 0;
    {
        int j = ustart + tid;
        int p = j >> 1;
        int wi = ((p >> 4) << 4) + (((p >> 3) & 1) << 1) + ((p >> 2) & 1) + ((p & 3) << 2);
        pub_off = wi * 2 + (j & 1);
    }
    // pre-loop: zero hx buffer for step 0 (256 threads x 16B = full 4KB)
    ((uint4 *)hxw)[tid] = make_uint4(0u, 0u, 0u, 0u);
    __syncthreads();

    const uint4 *hxp = hx4 + (h * 32) * 4 + kc;

    for (int t = 0; t < S_LEN; t++) {
        // ---- hoisted conv-scalar load: issued ~1500 cyc before epilogue use ----
        float ct = 0.f;
        if (w == 0) ct = __ldg(&g_c[t]);

        // ---- matvec: 64 HMMA.16816 per warp, 4 independent accumulator chains ----
        // (hxw for step t was staged by warp 1 in the previous iteration)
        float c0[4] = {0.f, 0.f, 0.f, 0.f};
        float c1[4] = {0.f, 0.f, 0.f, 0.f};
        float c2[4] = {0.f, 0.f, 0.f, 0.f};
        float c3[4] = {0.f, 0.f, 0.f, 0.f};
        uint4 bv;
        #pragma unroll
        for (int m = 0; m < M_TOT; m++) {
            if ((m & 1) == 0) bv = hxp[(m >> 1) * 4];
            uint4 av = (m < R_REG) ? areg[m] : wsw[(m - R_REG) * 32];
            unsigned blo = (m & 1) ? bv.z : bv.x;
            unsigned bhi = (m & 1) ? bv.w : bv.y;
            float *C = ((m & 3) == 0) ? c0 : ((m & 3) == 1) ? c1 : ((m & 3) == 2) ? c2 : c3;
            asm("mma.sync.aligned.m16n8k16.row.col.f32.f16.f16.f32 "
                "{%0,%1,%2,%3},{%4,%5,%6,%7},{%8,%9},{%0,%1,%2,%3};"
                : "+f"(C[0]), "+f"(C[1]), "+f"(C[2]), "+f"(C[3])
                : "r"(av.x), "r"(av.y), "r"(av.z), "r"(av.w),
                  "r"(blo), "r"(bhi));
        }

        // ---- export partial dots ----
        if ((lane & 3) == 0) {
            int r = lane >> 2;
            red[h * 64 + g * 16 + r]     = c0[0] + c1[0] + c2[0] + c3[0];
            red[h * 64 + g * 16 + 8 + r] = c0[2] + c1[2] + c2[2] + c3[2];
        }
        __syncthreads();   // all hxw reads done; exports visible to warp 0

        // ---- poller + stager (warp 1): detect global step-t completion, then
        //      stage hx(t) into hxw for step t+1 (concurrent with warp 0 epilogue)
        if (w == 1) {
            const unsigned tgt = (unsigned)NCTA * (unsigned)(t + 1);
            while (bar_ld(&g_bar) < tgt) { }   // same-address: one coalesced request
            const uint4 *gp = (const uint4 *)(g_img + (size_t)t * HID);
            #pragma unroll
            for (int k = 0; k < 8; k++) {
                uint4 v = ld_cg4(gp + lane + 32 * k);
                ((uint4 *)hxw)[lane + 32 * k] = v;
            }
        }

        // ---- epilogue (warp 0): gates, state, publish, release-arrive ----
        if (w == 0) {
            if (tid < U) {
                float4 ra = *(const float4 *)&red[tid * 4];
                float4 rb = *(const float4 *)&red[64 + tid * 4];
                float a0 = ra.x + rb.x + ct * w0r[0] + br[0];
                float a1 = ra.y + rb.y + ct * w0r[1] + br[1];
                float a2 = ra.z + rb.z + ct * w0r[2] + br[2];
                float a3 = ra.w + rb.w + ct * w0r[3] + br[3];
                float f  = sigm(a0);
                float ii = sigm(a1);
                float gg = tanh_fast(a2);
                float oo = sigm(a3);
                cx = f * cx + ii * gg;
                hv = oo * tanh_fast(cx);
                // publish pre-permuted f16 (ordered by syncwarp + red.release below)
                unsigned short hb = __half_as_ushort(__float2half_rn(hv));
                asm volatile("st.global.cg.u16 [%0],%1;"
                             :: "l"(g_img + (size_t)t * HID + pub_off), "h"(hb));
            }
            __syncwarp();
            if (tid == 0) bar_red(&g_bar);   // release-arrive covers the warp's stores
            // f32 output row: off the critical path, no cross-SM ordering needed
            if (tid < U) out[(size_t)t * HID + ustart + tid] = hv;
        }
        __syncthreads();   // staged hxw + next-step reuse of red[] both ordered here
    }

    // final hx / cx rows (state lives in warp-0 lanes)
    if (w == 0 && tid < U) {
        int j = ustart + tid;
        out[SH_TOT + j]       = hv;
        out[SH_TOT + HID + j] = cx;
    }
}

// ---------------- launch ----------------
extern "C" void kernel_launch(void *const *d_in, const int *in_sizes, int n_in,
                              void *d_out, int out_size) {
    const float *inputs = nullptr, *cw = nullptr, *cb = nullptr, *wg = nullptr, *bg = nullptr;
    for (int i = 0; i < n_in; i++) {
        switch (in_sizes[i]) {
            case S_LEN * 4:        inputs = (const float *)d_in[i]; break;
            case 4:                cw     = (const float *)d_in[i]; break;
            case 1:                cb     = (const float *)d_in[i]; break;
            case 2049 * 4 * HID:   wg     = (const float *)d_in[i]; break;
            case 4 * HID:          bg     = (const float *)d_in[i]; break;
        }
    }
    float *out = (float *)d_out;

    static bool attr_set = false;
    if (!attr_set) {
        cudaFuncSetAttribute(lstm_main, cudaFuncAttributeMaxDynamicSharedMemorySize, SMEM_BYTES);
        attr_set = true;
    }

    prep_all<<<(int)((NFRAG + 255) / 256), 256>>>(wg, inputs, cw, cb, bg);
    lstm_main<<<NCTA, NTHR, SMEM_BYTES>>>(out);
}